// round 15
// baseline (speedup 1.0000x reference)
#include <cuda_runtime.h>
#include <cuda_fp16.h>
#include <mma.h>
#include <math.h>
#include <stdint.h>

using namespace nvcuda;

#define BATCH 2
#define SEQ   2048
#define NH    16
#define DH    128
#define DM    2048
#define NQ    ((size_t)BATCH*NH*SEQ*DH)
#define QSCALE 0.08838834764831845f

// g_qkv: part 0 (Q, pre-scaled by 1/sqrt(d)), 1 (K): [b,h,s,d]; part 2 (V): [b,h,d,s]
__device__ __half g_qkv[3*(size_t)BATCH*NH*SEQ*DH];
__device__ __half g_attn[(size_t)BATCH*SEQ*DM];
__device__ __half g_xt[(size_t)BATCH*SEQ*DM];
__device__ __half g_wq[(size_t)DM*3*DM];   // W_qkv^T [6144][2048]
__device__ __half g_wo[(size_t)DM*DM];     // W_out   [2048][2048] row-major

// ---------------------------------------------------------------------------
__device__ __forceinline__ uint32_t smem_u32(const void* p) {
    return (uint32_t)__cvta_generic_to_shared(p);
}
#define CP_ASYNC16(dst_u32, src_ptr) \
    asm volatile("cp.async.cg.shared.global [%0], [%1], 16;" :: "r"(dst_u32), "l"(src_ptr))
#define CP_COMMIT()   asm volatile("cp.async.commit_group;")
#define CP_WAIT(n)    asm volatile("cp.async.wait_group %0;" :: "n"(n))
#define BAR_PAIR(id)  asm volatile("bar.sync %0, 64;" :: "r"(id) : "memory")

__device__ __forceinline__ void mma_f16(float* d, const uint32_t* a, const uint32_t* b) {
    asm volatile(
        "mma.sync.aligned.m16n8k16.row.col.f32.f16.f16.f32 "
        "{%0,%1,%2,%3},{%4,%5,%6,%7},{%8,%9},{%0,%1,%2,%3};"
        : "+f"(d[0]), "+f"(d[1]), "+f"(d[2]), "+f"(d[3])
        : "r"(a[0]), "r"(a[1]), "r"(a[2]), "r"(a[3]), "r"(b[0]), "r"(b[1]));
}

__device__ __forceinline__ void ldsm4(uint32_t* r, uint32_t addr) {
    asm volatile("ldmatrix.sync.aligned.m8n8.x4.shared.b16 {%0,%1,%2,%3}, [%4];"
        : "=r"(r[0]), "=r"(r[1]), "=r"(r[2]), "=r"(r[3]) : "r"(addr));
}

// ---------------------------------------------------------------------------
// pre-passes: fp32 -> fp16
// ---------------------------------------------------------------------------
__global__ void cvt_f2h_kernel(const float* __restrict__ in,
                               __half* __restrict__ out, int n4)
{
    int i = blockIdx.x * blockDim.x + threadIdx.x;
    if (i < n4) {
        float4 v = ((const float4*)in)[i];
        __half2* o = (__half2*)(out + (size_t)i * 4);
        o[0] = __floats2half2_rn(v.x, v.y);
        o[1] = __floats2half2_rn(v.z, v.w);
    }
}

__global__ void transpose_f2h_kernel(const float* __restrict__ in,
                                     __half* __restrict__ out, int R, int C)
{
    __shared__ float t[32][33];
    const int c0 = blockIdx.x * 32, r0 = blockIdx.y * 32;
    #pragma unroll
    for (int i = 0; i < 32; i += 8)
        t[threadIdx.y + i][threadIdx.x] =
            in[(size_t)(r0 + threadIdx.y + i) * C + c0 + threadIdx.x];
    __syncthreads();
    #pragma unroll
    for (int i = 0; i < 32; i += 8)
        out[(size_t)(c0 + threadIdx.y + i) * R + r0 + threadIdx.x] =
            __float2half(t[threadIdx.x][threadIdx.y + i]);
}

// ---------------------------------------------------------------------------
// QKV GEMM fp16 (round-13 proven). Q part pre-scaled by 1/sqrt(d) at scatter.
// ---------------------------------------------------------------------------
#define GP 72
#define LA_BYTES (128*GP*2)
#define LSTAGE_B (2*LA_BYTES)
#define CS_PITCH 132
#define LGEMM_SMEM (3*LSTAGE_B)       // 110592 B

__global__ __launch_bounds__(256, 2)
void gemm_ldsm_kernel(const __half* __restrict__ Aglob, const __half* __restrict__ Bt,
                      const float* __restrict__ bias,
                      int M, int N, int K)
{
    extern __shared__ char smc[];
    float* Cs = (float*)smc;

    const int tid  = threadIdx.x;
    const int warp = tid >> 5, lane = tid & 31;
    const int wr   = warp >> 1;
    const int wc   = warp & 1;
    const int g    = lane >> 2, tq = lane & 3;
    const int rowBlock = blockIdx.y * 128;
    const int colBlock = blockIdx.x * 128;

    const int ldRow = tid >> 3;
    const int ldCh  = tid & 7;
    const __half* Asrc = Aglob + (size_t)(rowBlock + ldRow) * K + ldCh * 8;
    const __half* Bsrc = Bt + (size_t)(colBlock + ldRow) * K + ldCh * 8;

    const uint32_t smBase = smem_u32(smc);
    const uint32_t ldOff  = (uint32_t)((ldRow * GP + ldCh * 8) * 2);

    uint32_t aOff[2];
    #pragma unroll
    for (int mi = 0; mi < 2; mi++)
        aOff[mi] = (uint32_t)(((wr * 32 + mi * 16 + (lane & 15)) * GP + (lane >> 4) * 8) * 2);
    uint32_t bOff[4];
    #pragma unroll
    for (int p = 0; p < 4; p++)
        bOff[p] = (uint32_t)(LA_BYTES +
                  ((wc * 64 + p * 16 + (lane & 7) + ((lane >> 4) << 3)) * GP
                   + ((lane >> 3) & 1) * 8) * 2);

    float acc[2][8][4] = {};
    const int NIT = K >> 6;

    auto issue = [&](int tt, int s) {
        const int k0 = tt << 6;
        const uint32_t sb = smBase + (uint32_t)s * LSTAGE_B;
        #pragma unroll
        for (int i = 0; i < 4; i++)
            CP_ASYNC16(sb + ldOff + (uint32_t)(i * 32 * GP * 2),
                       Asrc + (size_t)(i * 32) * K + k0);
        #pragma unroll
        for (int i = 0; i < 4; i++)
            CP_ASYNC16(sb + (uint32_t)LA_BYTES + ldOff + (uint32_t)(i * 32 * GP * 2),
                       Bsrc + (size_t)(i * 32) * K + k0);
        CP_COMMIT();
    };

    issue(0, 0);

    for (int t = 0; t < NIT; t++) {
        if (t + 1 < NIT) {
            issue(t + 1, (t + 1) % 3);
            CP_WAIT(1);
        } else {
            CP_WAIT(0);
        }
        __syncthreads();

        const uint32_t sb = smBase + (uint32_t)(t % 3) * LSTAGE_B;
        #pragma unroll
        for (int ks = 0; ks < 4; ks++) {
            const uint32_t kb = (uint32_t)(ks * 32);
            uint32_t a0[4], a1[4];
            ldsm4(a0, sb + aOff[0] + kb);
            ldsm4(a1, sb + aOff[1] + kb);
            #pragma unroll
            for (int p = 0; p < 4; p++) {
                uint32_t bb[4];
                ldsm4(bb, sb + bOff[p] + kb);
                mma_f16(acc[0][2*p  ], a0, bb);
                mma_f16(acc[0][2*p+1], a0, bb + 2);
                mma_f16(acc[1][2*p  ], a1, bb);
                mma_f16(acc[1][2*p+1], a1, bb + 2);
            }
        }
    }
    __syncthreads();

    #pragma unroll
    for (int mi = 0; mi < 2; mi++) {
        const int r_lo = wr * 32 + mi * 16 + g;
        #pragma unroll
        for (int j = 0; j < 8; j++) {
            const int col = wc * 64 + j * 8 + 2 * tq;
            *(float2*)&Cs[r_lo * CS_PITCH + col] =
                make_float2(acc[mi][j][0], acc[mi][j][1]);
            *(float2*)&Cs[(r_lo + 8) * CS_PITCH + col] =
                make_float2(acc[mi][j][2], acc[mi][j][3]);
        }
    }
    __syncthreads();

    #pragma unroll
    for (int it = 0; it < 16; it++) {
        int u = tid + it * 256;
        int row = u >> 5, c4 = (u & 31) * 4;
        float4 v = *(float4*)&Cs[row * CS_PITCH + c4];
        const int gcol = colBlock + c4;
        v.x += bias[gcol + 0]; v.y += bias[gcol + 1];
        v.z += bias[gcol + 2]; v.w += bias[gcol + 3];
        const int gr = rowBlock + row;
        const int part = gcol >> 11;
        const int c2   = gcol & 2047;
        const int h    = c2 >> 7;
        const int d0   = c2 & 127;
        const int bb   = gr >> 11;
        const int s    = gr & 2047;
        if (part == 2) {
            __half* dstv = g_qkv + 2 * NQ
                         + (((size_t)(bb * NH + h)) * DH + d0) * SEQ + s;
            dstv[0 * SEQ] = __float2half(v.x);
            dstv[1 * SEQ] = __float2half(v.y);
            dstv[2 * SEQ] = __float2half(v.z);
            dstv[3 * SEQ] = __float2half(v.w);
        } else {
            if (part == 0) {   // pre-scale Q by 1/sqrt(d)
                v.x *= QSCALE; v.y *= QSCALE; v.z *= QSCALE; v.w *= QSCALE;
            }
            __half* dst = g_qkv + (size_t)part * NQ
                        + (((size_t)(bb * NH + h) * SEQ) + s) * DH + d0;
            __half2* d2 = (__half2*)dst;
            d2[0] = __floats2half2_rn(v.x, v.y);
            d2[1] = __floats2half2_rn(v.z, v.w);
        }
    }
}

// ---------------------------------------------------------------------------
// Out-projection GEMM fp16 wmma 3-stage (round-13 proven, unchanged).
// ---------------------------------------------------------------------------
#define WAP 72
#define WBP 136
#define WA_BYTES (128*WAP*2)
#define WSTAGE_B (WA_BYTES + 64*WBP*2)
#define WGEMM_SMEM (3*WSTAGE_B)           // 107520 B

__global__ __launch_bounds__(256, 2)
void gemm_wmma_kernel(const __half* __restrict__ B,
                      const float* __restrict__ bias, float* __restrict__ C,
                      int M, int N, int K)
{
    extern __shared__ char smc[];
    float* Cs = (float*)smc;

    const __half* Abase = (const __half*)g_attn;

    const int tid  = threadIdx.x;
    const int warp = tid >> 5;
    const int wr   = warp >> 1;
    const int wc   = warp & 1;
    const int rowBlock = blockIdx.y * 128;
    const int colBlock = blockIdx.x * 128;

    const int aRow = tid >> 3, aCh = tid & 7;
    const int bRow = tid >> 4, bCh = tid & 15;
    const __half* Asrc = Abase + (size_t)(rowBlock + aRow) * K + aCh * 8;
    const __half* Bsrc = B + (size_t)bRow * N + colBlock + bCh * 8;

    const uint32_t smBase = smem_u32(smc);
    const uint32_t aOffB  = (uint32_t)((aRow * WAP + aCh * 8) * 2);
    const uint32_t bOffB  = (uint32_t)(WA_BYTES + (bRow * WBP + bCh * 8) * 2);

    wmma::fragment<wmma::accumulator, 16, 16, 16, float> acc[2][4];
    #pragma unroll
    for (int i = 0; i < 2; i++)
        #pragma unroll
        for (int j = 0; j < 4; j++)
            wmma::fill_fragment(acc[i][j], 0.0f);

    const int NIT = K >> 6;

    auto issue = [&](int tt, int s) {
        const int k0 = tt << 6;
        const uint32_t sb = smBase + (uint32_t)s * WSTAGE_B;
        #pragma unroll
        for (int it = 0; it < 4; it++)
            CP_ASYNC16(sb + aOffB + (uint32_t)(it * 32 * WAP * 2),
                       Asrc + (size_t)(it * 32) * K + k0);
        #pragma unroll
        for (int it = 0; it < 4; it++)
            CP_ASYNC16(sb + bOffB + (uint32_t)(it * 16 * WBP * 2),
                       Bsrc + (size_t)(k0 + it * 16) * N);
        CP_COMMIT();
    };

    issue(0, 0);

    for (int t = 0; t < NIT; t++) {
        if (t + 1 < NIT) {
            issue(t + 1, (t + 1) % 3);
            CP_WAIT(1);
        } else {
            CP_WAIT(0);
        }
        __syncthreads();

        const __half* As = (const __half*)(smc + (t % 3) * WSTAGE_B);
        const __half* Bs = (const __half*)(smc + (t % 3) * WSTAGE_B + WA_BYTES);
        #pragma unroll
        for (int ks = 0; ks < 4; ks++) {
            wmma::fragment<wmma::matrix_a, 16, 16, 16, half, wmma::row_major> af[2];
            wmma::fragment<wmma::matrix_b, 16, 16, 16, half, wmma::row_major> bf[4];
            #pragma unroll
            for (int i = 0; i < 2; i++)
                wmma::load_matrix_sync(af[i], &As[(wr * 32 + i * 16) * WAP + ks * 16], WAP);
            #pragma unroll
            for (int j = 0; j < 4; j++)
                wmma::load_matrix_sync(bf[j], &Bs[(ks * 16) * WBP + wc * 64 + j * 16], WBP);
            #pragma unroll
            for (int i = 0; i < 2; i++)
                #pragma unroll
                for (int j = 0; j < 4; j++)
                    wmma::mma_sync(acc[i][j], af[i], bf[j], acc[i][j]);
        }
    }
    __syncthreads();

    #pragma unroll
    for (int i = 0; i < 2; i++)
        #pragma unroll
        for (int j = 0; j < 4; j++)
            wmma::store_matrix_sync(&Cs[(wr * 32 + i * 16) * CS_PITCH + wc * 64 + j * 16],
                                    acc[i][j], CS_PITCH, wmma::mem_row_major);
    __syncthreads();

    #pragma unroll
    for (int it = 0; it < 16; it++) {
        int u = tid + it * 256;
        int row = u >> 5, c4 = (u & 31) * 4;
        float4 v = *(float4*)&Cs[row * CS_PITCH + c4];
        const int gcol = colBlock + c4;
        v.x += bias[gcol + 0]; v.y += bias[gcol + 1];
        v.z += bias[gcol + 2]; v.w += bias[gcol + 3];
        const int gr = rowBlock + row;
        *(float4*)(C + (size_t)gr * N + gcol) = v;
    }
}

// ---------------------------------------------------------------------------
// Causal flash attention v8 (fp16): in-register softmax, pair-local barriers.
// 128-q tile, 512 threads, 2-stage KV ring, all operands via ldmatrix.
// smem: 2 KV stages (35840 B each) + Ps half[128][72] + stats[128][2] fp32.
// Row state (m, l) lives in registers (replicated across quad lanes).
// ---------------------------------------------------------------------------
#define FPH 136
#define VPH 72
#define PPH 72
#define KVS_B (64*FPH*2 + 128*VPH*2)       // 35840 B
#define FLASH_SMEM (2*KVS_B + 128*PPH*2 + 256*4)   // 91136 B

__global__ __launch_bounds__(512)
void flash_kernel()
{
    extern __shared__ char smc[];
    __half* Ps  = (__half*)(smc + 2 * KVS_B);
    float* xbuf = (float*)(smc + 2 * KVS_B + 128 * PPH * 2);   // [128][2]

    const int qt = (int)(gridDim.x - 1) - (int)blockIdx.x;
    const int h = blockIdx.y, b = blockIdx.z;
    const int bh = b * NH + h;

    const __half* Qp = g_qkv + 0 * NQ + ((size_t)bh * SEQ + qt * 128) * DH;
    const __half* Kp = g_qkv + 1 * NQ + (size_t)bh * SEQ * DH;
    const __half* Vp = g_qkv + 2 * NQ + (size_t)bh * DH * SEQ;

    const int tid  = threadIdx.x;
    const int warp = tid >> 5, lane = tid & 31;
    const int wr = warp >> 1, wc = warp & 1;
    const int g  = lane >> 2, tq = lane & 3;
    const int sr = wr * 16;
    const int sn0 = wc * 32;
    const int barid = wr + 1;

    // ldmatrix lane byte-offsets
    const uint32_t qOff  = (uint32_t)(((sr + (lane & 15)) * FPH + (lane >> 4) * 8) * 2);
    const uint32_t kOff0 = (uint32_t)(((wc * 32 + (lane & 7) + ((lane >> 4) << 3)) * FPH
                                      + ((lane >> 3) & 1) * 8) * 2);
    const uint32_t kOff1 = kOff0 + (uint32_t)(16 * FPH * 2);
    const uint32_t pOff  = (uint32_t)(((sr + (lane & 15)) * PPH + (lane >> 4) * 8) * 2);
    uint32_t vOff[4];
    #pragma unroll
    for (int p = 0; p < 4; p++)
        vOff[p] = (uint32_t)(((wc * 64 + p * 16 + (lane & 7) + ((lane >> 4) << 3)) * VPH
                             + ((lane >> 3) & 1) * 8) * 2);
    const uint32_t psB = smem_u32(Ps);

    auto issueKV = [&](int kt, int s) {
        const __half* Kt = Kp + (size_t)kt * 64 * DH;
        const __half* Vt = Vp + (size_t)kt * 64;
        const uint32_t kB = smem_u32(smc + s * KVS_B);
        const uint32_t vB = kB + (uint32_t)(64 * FPH * 2);
        #pragma unroll
        for (int it = 0; it < 2; it++) {
            int u = tid + it * 512;
            int kr = u >> 4, kc = u & 15;
            CP_ASYNC16(kB + (uint32_t)((kr * FPH + kc * 8) * 2), Kt + kr * DH + kc * 8);
            int vr = u >> 3, vc = u & 7;
            CP_ASYNC16(vB + (uint32_t)((vr * VPH + vc * 8) * 2), Vt + (size_t)vr * SEQ + vc * 8);
        }
        CP_COMMIT();
    };

    issueKV(0, 0);
    {
        __half* Qtmp = (__half*)(smc + KVS_B);
        #pragma unroll
        for (int it = 0; it < 4; it++) {
            int u = tid + it * 512;
            int r = u >> 4, c = u & 15;
            *(uint4*)&Qtmp[r * FPH + c * 8] = *(const uint4*)(Qp + r * DH + c * 8);
        }
    }
    __syncthreads();

    uint32_t qf[8][4];
    {
        const uint32_t qB = smem_u32(smc + KVS_B);
        #pragma unroll
        for (int ks = 0; ks < 8; ks++)
            ldsm4(qf[ks], qB + qOff + (uint32_t)(ks * 32));
    }
    __syncthreads();   // qf done before issueKV(1,1) overwrites stage 1

    float oc[8][4];
    #pragma unroll
    for (int t = 0; t < 8; t++)
        #pragma unroll
        for (int i = 0; i < 4; i++) oc[t][i] = 0.f;

    float m_reg[2] = {-1e30f, -1e30f};
    float l_reg[2] = {0.f, 0.f};

    const int ktMax = 2 * qt + 1;
    for (int kt = 0; kt <= ktMax; kt++) {
        const int buf = kt & 1;
        const uint32_t kBase = smem_u32(smc + buf * KVS_B);
        const uint32_t vBase = kBase + (uint32_t)(64 * FPH * 2);

        if (kt < ktMax) {
            issueKV(kt + 1, buf ^ 1);
            CP_WAIT(1);
        } else {
            CP_WAIT(0);
        }
        __syncthreads();                     // [B] KV(kt) visible

        // ---- S = Q K^T (Q pre-scaled) ----
        float sc[4][4] = {};
        #pragma unroll
        for (int ks = 0; ks < 8; ks++) {
            const uint32_t kb = (uint32_t)(ks * 32);
            uint32_t b0[4], b1[4];
            ldsm4(b0, kBase + kOff0 + kb);
            ldsm4(b1, kBase + kOff1 + kb);
            mma_f16(sc[0], qf[ks], b0);
            mma_f16(sc[1], qf[ks], b0 + 2);
            mma_f16(sc[2], qf[ks], b1);
            mma_f16(sc[3], qf[ks], b1 + 2);
        }

        // ---- causal mask (in regs) ----
        if (kt >= 2 * qt) {
            const int rlo = qt * 128 + sr + g;
            #pragma unroll
            for (int t = 0; t < 4; t++) {
                const int c0 = kt * 64 + sn0 + t * 8 + 2 * tq;
                if (c0     > rlo    ) sc[t][0] = -1e30f;
                if (c0 + 1 > rlo    ) sc[t][1] = -1e30f;
                if (c0     > rlo + 8) sc[t][2] = -1e30f;
                if (c0 + 1 > rlo + 8) sc[t][3] = -1e30f;
            }
        }

        // ---- in-register softmax: row stats in regs, cross-warp via smem ----
        {
            float mx0 = fmaxf(fmaxf(sc[0][0], sc[0][1]), fmaxf(sc[1][0], sc[1][1]));
            mx0 = fmaxf(mx0, fmaxf(fmaxf(sc[2][0], sc[2][1]), fmaxf(sc[3][0], sc[3][1])));
            float mx1 = fmaxf(fmaxf(sc[0][2], sc[0][3]), fmaxf(sc[1][2], sc[1][3]));
            mx1 = fmaxf(mx1, fmaxf(fmaxf(sc[2][2], sc[2][3]), fmaxf(sc[3][2], sc[3][3])));
            mx0 = fmaxf(mx0, __shfl_xor_sync(0xffffffffu, mx0, 1));
            mx0 = fmaxf(mx0, __shfl_xor_sync(0xffffffffu, mx0, 2));
            mx1 = fmaxf(mx1, __shfl_xor_sync(0xffffffffu, mx1, 1));
            mx1 = fmaxf(mx1, __shfl_xor_sync(0xffffffffu, mx1, 2));
            if (tq == 0) {
                xbuf[(sr + g) * 2 + wc]     = mx0;
                xbuf[(sr + g + 8) * 2 + wc] = mx1;
            }
            BAR_PAIR(barid);                 // pair-local max exchange
            mx0 = fmaxf(mx0, xbuf[(sr + g) * 2 + (wc ^ 1)]);
            mx1 = fmaxf(mx1, xbuf[(sr + g + 8) * 2 + (wc ^ 1)]);

            const float mn0 = fmaxf(m_reg[0], mx0);
            const float mn1 = fmaxf(m_reg[1], mx1);
            const float a0 = __expf(m_reg[0] - mn0);
            const float a1 = __expf(m_reg[1] - mn1);
            m_reg[0] = mn0; m_reg[1] = mn1;

            float rs0 = 0.f, rs1 = 0.f;
            #pragma unroll
            for (int t = 0; t < 4; t++) {
                float p0 = __expf(sc[t][0] - mn0);
                float p1 = __expf(sc[t][1] - mn0);
                float p2 = __expf(sc[t][2] - mn1);
                float p3 = __expf(sc[t][3] - mn1);
                rs0 += p0 + p1;
                rs1 += p2 + p3;
                const int col = sn0 + t * 8 + 2 * tq;
                *(__half2*)&Ps[(sr + g    ) * PPH + col] = __floats2half2_rn(p0, p1);
                *(__half2*)&Ps[(sr + g + 8) * PPH + col] = __floats2half2_rn(p2, p3);
            }
            rs0 += __shfl_xor_sync(0xffffffffu, rs0, 1);
            rs0 += __shfl_xor_sync(0xffffffffu, rs0, 2);
            rs1 += __shfl_xor_sync(0xffffffffu, rs1, 1);
            rs1 += __shfl_xor_sync(0xffffffffu, rs1, 2);
            l_reg[0] = l_reg[0] * a0 + rs0;
            l_reg[1] = l_reg[1] * a1 + rs1;

            #pragma unroll
            for (int t = 0; t < 8; t++) {
                oc[t][0] *= a0; oc[t][1] *= a0;
                oc[t][2] *= a1; oc[t][3] *= a1;
            }
        }
        BAR_PAIR(barid);                     // P (both halves) visible to pair

        // ---- O += P V ----
        #pragma unroll
        for (int ks = 0; ks < 4; ks++) {
            const uint32_t kb = (uint32_t)(ks * 32);
            uint32_t a[4];
            ldsm4(a, psB + pOff + kb);
            #pragma unroll
            for (int p = 0; p < 4; p++) {
                uint32_t vb[4];
                ldsm4(vb, vBase + vOff[p] + kb);
                mma_f16(oc[2*p  ], a, vb);
                mma_f16(oc[2*p+1], a, vb + 2);
            }
        }
        __syncthreads();                     // [A] buf reusable; P safe to rewrite
    }

    // ---- epilogue: merge l across warp pair, write O/l ----
    if (tq == 0) {
        xbuf[(sr + g) * 2 + wc]     = l_reg[0];
        xbuf[(sr + g + 8) * 2 + wc] = l_reg[1];
    }
    __syncthreads();
    {
        const float inv_lo = 1.0f / (xbuf[(sr + g) * 2] + xbuf[(sr + g) * 2 + 1]);
        const float inv_hi = 1.0f / (xbuf[(sr + g + 8) * 2] + xbuf[(sr + g + 8) * 2 + 1]);
        const int on0 = wc * 64;
        __half* Obase = g_attn + ((size_t)b * SEQ + qt * 128) * DM + h * DH;
        #pragma unroll
        for (int t = 0; t < 8; t++) {
            const int col = on0 + t * 8 + 2 * tq;
            *(__half2*)(Obase + (size_t)(sr + g    ) * DM + col) =
                __floats2half2_rn(oc[t][0] * inv_lo, oc[t][1] * inv_lo);
            *(__half2*)(Obase + (size_t)(sr + g + 8) * DM + col) =
                __floats2half2_rn(oc[t][2] * inv_hi, oc[t][3] * inv_hi);
        }
    }
}

// ---------------------------------------------------------------------------
extern "C" void kernel_launch(void* const* d_in, const int* in_sizes, int n_in,
                              void* d_out, int out_size)
{
    const float* x    = (const float*)d_in[0];
    const float* Wqkv = (const float*)d_in[1];
    const float* bqkv = (const float*)d_in[2];
    const float* Wout = (const float*)d_in[3];
    const float* bout = (const float*)d_in[4];
    float* out = (float*)d_out;

    const int M = BATCH * SEQ;

    cudaFuncSetAttribute(gemm_ldsm_kernel,
                         cudaFuncAttributeMaxDynamicSharedMemorySize, LGEMM_SMEM);
    cudaFuncSetAttribute(gemm_wmma_kernel,
                         cudaFuncAttributeMaxDynamicSharedMemorySize, WGEMM_SMEM);
    cudaFuncSetAttribute(flash_kernel,
                         cudaFuncAttributeMaxDynamicSharedMemorySize, FLASH_SMEM);

    __half* xt; __half* wq; __half* wo;
    cudaGetSymbolAddress((void**)&xt, g_xt);
    cudaGetSymbolAddress((void**)&wq, g_wq);
    cudaGetSymbolAddress((void**)&wo, g_wo);

    // 0) pre-pass
    cvt_f2h_kernel<<<(int)((size_t)BATCH*SEQ*DM/4/256), 256>>>(x, xt, (int)((size_t)BATCH*SEQ*DM/4));
    {
        dim3 blk(32, 8);
        transpose_f2h_kernel<<<dim3((3*DM)/32, DM/32), blk>>>(Wqkv, wq, DM, 3*DM);
    }
    cvt_f2h_kernel<<<(int)((size_t)DM*DM/4/256), 256>>>(Wout, wo, (int)((size_t)DM*DM/4));

    // 1) QKV projection (fp16 mma + ldmatrix; Q pre-scaled, V transposed)
    {
        dim3 grid((3 * DM) / 128, M / 128);
        gemm_ldsm_kernel<<<grid, 256, LGEMM_SMEM>>>(xt, wq, bqkv, M, 3 * DM, DM);
    }
    // 2) flash attention v8 (in-register softmax)
    {
        dim3 grid(SEQ / 128, NH, BATCH);
        flash_kernel<<<grid, 512, FLASH_SMEM>>>();
    }
    // 3) output projection (fp16 wmma) -> d_out fp32
    {
        dim3 grid(DM / 128, M / 128);
        gemm_wmma_kernel<<<grid, 256, WGEMM_SMEM>>>(wo, bout, out, M, DM, DM);
    }
}